// round 16
// baseline (speedup 1.0000x reference)
#include <cuda_runtime.h>
#include <cstdint>

// out[2048,122880] = tile(x1[2048,4096] @ x2[4096,4096], 30x), fp32.
// R16 = R15 (split-int8 IMMA) + spread-LDS kt body, 5-stage pipeline,
// shuffle-packed STG.128 epilogue, fully-parallel scales reduction.
#define MDIM 2048
#define NDIM 4096
#define KDIM 4096
#define NREP 30
#define OUTN (NDIM * NREP)
#define NKG (KDIM / 32)          // 128 k32 groups
#define STAGES 5

// fragment-ordered int8 operands
__device__ uint4 g_Ah[(size_t)128 * 128 * 32];   // [m16][k32][lane]
__device__ uint4 g_Al[(size_t)128 * 128 * 32];
__device__ uint4 g_Bh[(size_t)256 * 128 * 32];   // [n16pair][k32][lane]
__device__ uint4 g_Bl[(size_t)256 * 128 * 32];
__device__ int   g_sa[MDIM];                     // row maxabs of A (float-as-int, >=0)
__device__ int   g_sb[NDIM];                     // col maxabs of B (float-as-int, >=0)

__device__ __forceinline__ uint32_t smem_u32(const void* p) {
    uint32_t a;
    asm("{ .reg .u64 t; cvta.to.shared.u64 t, %1; cvt.u32.u64 %0, t; }" : "=r"(a) : "l"(p));
    return a;
}
__device__ __forceinline__ void cp_async16(uint32_t dst, const void* src) {
    asm volatile("cp.async.cg.shared.global [%0], [%1], 16;" :: "r"(dst), "l"(src) : "memory");
}
#define CP_COMMIT() asm volatile("cp.async.commit_group;" ::: "memory")
#define CP_WAIT3()  asm volatile("cp.async.wait_group 3;" ::: "memory")

__device__ __forceinline__ void imma(int c[4], uint4 a, uint32_t b0, uint32_t b1) {
    asm volatile(
        "mma.sync.aligned.m16n8k32.row.col.s32.s8.s8.s32 "
        "{%0,%1,%2,%3},{%4,%5,%6,%7},{%8,%9},{%0,%1,%2,%3};"
        : "+r"(c[0]), "+r"(c[1]), "+r"(c[2]), "+r"(c[3])
        : "r"(a.x), "r"(a.y), "r"(a.z), "r"(a.w), "r"(b0), "r"(b1));
}

// ---------------- kernel 1: scales, fully parallel ----------------
// blocks [0,512): A — 512 blocks x 8 warps = 4096 tasks = 2048 rows x 2 halves;
//   each warp reduces an 8KB half-row, lane0 atomicMax.
// blocks [512,1024): B — 32 k-chunks(128 rows) x 16 n-chunks(256 cols);
//   each thread reduces 128 strided elements of one column, atomicMax.
// (maxabs >= 0 so float ordering == int bit ordering; globals zero-init; max is
//  idempotent across graph replays -> deterministic.)
__global__ __launch_bounds__(256)
void scales_kernel(const float* __restrict__ A, const float* __restrict__ B) {
    const int tid = threadIdx.x, lane = tid & 31, warp = tid >> 5;
    if (blockIdx.x < 512) {
        const int m    = blockIdx.x * 4 + (warp >> 1);
        const int half = warp & 1;
        const float4* a4 = (const float4*)(A + (size_t)m * KDIM + half * 2048);
        float mx = 0.0f;
        #pragma unroll 4
        for (int i = 0; i < 16; i++) {
            float4 v = a4[lane + i * 32];
            mx = fmaxf(mx, fmaxf(fmaxf(fabsf(v.x), fabsf(v.y)),
                                 fmaxf(fabsf(v.z), fabsf(v.w))));
        }
        #pragma unroll
        for (int o = 16; o; o >>= 1) mx = fmaxf(mx, __shfl_xor_sync(0xffffffffu, mx, o));
        if (lane == 0) atomicMax(&g_sa[m], __float_as_int(mx));
    } else {
        const int id = blockIdx.x - 512;
        const int kc = id >> 4;           // 0..31, 128 rows each
        const int nc = id & 15;           // 0..15, 256 cols each
        const int n  = nc * 256 + tid;
        const float* __restrict__ bp = B + (size_t)(kc * 128) * NDIM + n;
        float mx = 0.0f;
        #pragma unroll 8
        for (int k = 0; k < 128; k++)
            mx = fmaxf(mx, fabsf(bp[(size_t)k * NDIM]));
        atomicMax(&g_sb[n], __float_as_int(mx));
    }
}

__device__ __forceinline__ uint32_t pack4(const int h[4]) {
    return (uint32_t)(h[0] & 0xff) | ((uint32_t)(h[1] & 0xff) << 8) |
           ((uint32_t)(h[2] & 0xff) << 16) | ((uint32_t)(h[3] & 0xff) << 24);
}

// ---------------- kernel 2: quantize + fragment-pack ----------------
// blocks [0,1024): A (m16 x k512); blocks [1024,3072): B (k128 x n64)
__global__ __launch_bounds__(256)
void prep_kernel(const float* __restrict__ A, const float* __restrict__ B) {
    __shared__ float sbuf[128 * 68];     // A view 16x516, B view 128x68
    __shared__ float inv_s[64];
    const int tid = threadIdx.x, lane = tid & 31, warp = tid >> 5;
    const int g = lane >> 2, t = lane & 3;

    if (blockIdx.x < 1024) {
        const int bx = blockIdx.x & 7;    // K/512
        const int m16 = blockIdx.x >> 3;  // M/16
        #pragma unroll
        for (int i = 0; i < 8; i++) {
            const int idx = i * 256 + tid;
            const int rr = idx >> 7, c4 = idx & 127;
            *(float4*)&sbuf[rr * 516 + c4 * 4] =
                *(const float4*)&A[(size_t)(m16 * 16 + rr) * KDIM + bx * 512 + c4 * 4];
        }
        if (tid < 16) {
            float mx = __int_as_float(g_sa[m16 * 16 + tid]);
            inv_s[tid] = mx > 0.0f ? 127.0f / mx : 0.0f;
        }
        __syncthreads();
        const float ia0 = inv_s[g], ia1 = inv_s[g + 8];
        auto pk = [&](int row, int c0, float ia, uint32_t& h4, uint32_t& l4) {
            int hh[4], ll[4];
            #pragma unroll
            for (int j = 0; j < 4; j++) {
                float q = sbuf[row * 516 + c0 + j] * ia;
                float hf = rintf(q);
                hh[j] = (int)hf;
                ll[j] = (int)rintf((q - hf) * 128.0f);
            }
            h4 = pack4(hh); l4 = pack4(ll);
        };
        #pragma unroll
        for (int i = 0; i < 2; i++) {
            const int kgl = warp * 2 + i;        // 0..15
            const int kb = kgl * 32;
            uint4 H, L;
            pk(g,     kb + 4 * t,      ia0, H.x, L.x);
            pk(g + 8, kb + 4 * t,      ia1, H.y, L.y);
            pk(g,     kb + 16 + 4 * t, ia0, H.z, L.z);
            pk(g + 8, kb + 16 + 4 * t, ia1, H.w, L.w);
            const size_t o = ((size_t)m16 * 128 + bx * 16 + kgl) * 32 + lane;
            g_Ah[o] = H; g_Al[o] = L;
        }
    } else {
        const int id = blockIdx.x - 1024;
        const int bx = id & 31;           // K/128
        const int by = id >> 5;           // N/64
        #pragma unroll
        for (int i = 0; i < 8; i++) {
            const int idx = i * 256 + tid;
            const int kr = idx >> 4, c4 = idx & 15;
            *(float4*)&sbuf[kr * 68 + c4 * 4] =
                *(const float4*)&B[(size_t)(bx * 128 + kr) * NDIM + by * 64 + c4 * 4];
        }
        if (tid < 64) {
            float mx = __int_as_float(g_sb[by * 64 + tid]);
            inv_s[tid] = mx > 0.0f ? 127.0f / mx : 0.0f;
        }
        __syncthreads();
        auto pk = [&](int col, int k0, float ib, uint32_t& h4, uint32_t& l4) {
            int hh[4], ll[4];
            #pragma unroll
            for (int j = 0; j < 4; j++) {
                float q = sbuf[(k0 + j) * 68 + col] * ib;
                float hf = rintf(q);
                hh[j] = (int)hf;
                ll[j] = (int)rintf((q - hf) * 128.0f);
            }
            h4 = pack4(hh); l4 = pack4(ll);
        };
        #pragma unroll
        for (int i = 0; i < 2; i++) {
            const int id2 = warp * 2 + i;        // 16 items: 4 n16p x 4 kgl
            const int n16l = id2 >> 2, kgl = id2 & 3;
            const int c0 = n16l * 16 + g, c1 = c0 + 8;
            const float ib0 = inv_s[c0], ib1 = inv_s[c1];
            const int kb = kgl * 32;
            uint4 H, L;
            pk(c0, kb + 4 * t,      ib0, H.x, L.x);
            pk(c0, kb + 16 + 4 * t, ib0, H.y, L.y);
            pk(c1, kb + 4 * t,      ib1, H.z, L.z);
            pk(c1, kb + 16 + 4 * t, ib1, H.w, L.w);
            const size_t o = (((size_t)by * 4 + n16l) * 128 + bx * 4 + kgl) * 32 + lane;
            g_Bh[o] = H; g_Bl[o] = L;
        }
    }
}

// ---------------- GEMM: 64x64 CTA, 4 warps of 32x32, int8 split, 5-stage ----------------
// stage (8KB): Ah@0 Al@2048 Bh@4096 Bl@6144, each 128 uint4
__global__ __launch_bounds__(128, 4)
void Model_82454782148931_gemm(float* __restrict__ out) {
    __shared__ char smem[STAGES * 8192];      // 40KB static
    const uint32_t sbase = smem_u32(smem);
    const int tid  = threadIdx.x;
    const int lane = tid & 31;
    const int warp = tid >> 5;
    const int wm   = warp & 1;              // 0..1 -> 32-row slab
    const int wn   = warp >> 1;             // 0..1 -> 32-col slab
    const int cm   = blockIdx.x & 31;       // m fastest: wave shares A in L2
    const int cn   = blockIdx.x >> 5;       // 0..63
    const int bm16c  = cm * 4;              // 4 m16 tiles per CTA
    const int bn16pc = cn * 4;              // 4 n16-pair tiles per CTA

    int chh[2][4][4], cx[2][4][4];
    #pragma unroll
    for (int mt = 0; mt < 2; mt++)
        #pragma unroll
        for (int nt = 0; nt < 4; nt++)
            #pragma unroll
            for (int i = 0; i < 4; i++) { chh[mt][nt][i] = 0; cx[mt][nt][i] = 0; }

    const int m16l = tid >> 5;              // thread's load row-tile (=warp)
    const int ln   = tid & 31;
    auto load_stage = [&](int s, int kt) {
        const uint32_t ab = sbase + s * 8192;
        cp_async16(ab + tid * 16,        &g_Ah[((size_t)(bm16c + m16l) * 128 + kt) * 32 + ln]);
        cp_async16(ab + 2048 + tid * 16, &g_Al[((size_t)(bm16c + m16l) * 128 + kt) * 32 + ln]);
        cp_async16(ab + 4096 + tid * 16, &g_Bh[((size_t)(bn16pc + m16l) * 128 + kt) * 32 + ln]);
        cp_async16(ab + 6144 + tid * 16, &g_Bl[((size_t)(bn16pc + m16l) * 128 + kt) * 32 + ln]);
    };

    load_stage(0, 0); CP_COMMIT();
    load_stage(1, 1); CP_COMMIT();
    load_stage(2, 2); CP_COMMIT();
    load_stage(3, 3); CP_COMMIT();

    const int aoff0 = ((wm * 2 + 0) * 32 + lane) * 16;
    const int aoff1 = ((wm * 2 + 1) * 32 + lane) * 16;
    const int boff0 = ((wn * 2 + 0) * 32 + lane) * 16;
    const int boff1 = ((wn * 2 + 1) * 32 + lane) * 16;

    #pragma unroll 1
    for (int kt = 0; kt < NKG; kt++) {
        const int s = kt % STAGES;
        CP_WAIT3();                          // stage kt landed (kt+1..kt+3 in flight)
        __syncthreads();
        if (kt + 4 < NKG) load_stage((kt + 4) % STAGES, kt + 4);
        CP_COMMIT();

        const char* base = smem + s * 8192;
        // phase 1: h operands + hh IMMAs
        uint4 ah0 = *(const uint4*)(base + aoff0);
        uint4 ah1 = *(const uint4*)(base + aoff1);
        uint4 bh0 = *(const uint4*)(base + 4096 + boff0);
        uint4 bh1 = *(const uint4*)(base + 4096 + boff1);
        imma(chh[0][0], ah0, bh0.x, bh0.y); imma(chh[0][1], ah0, bh0.z, bh0.w);
        imma(chh[0][2], ah0, bh1.x, bh1.y); imma(chh[0][3], ah0, bh1.z, bh1.w);
        imma(chh[1][0], ah1, bh0.x, bh0.y); imma(chh[1][1], ah1, bh0.z, bh0.w);
        imma(chh[1][2], ah1, bh1.x, bh1.y); imma(chh[1][3], ah1, bh1.z, bh1.w);
        // phase 2: bl + h*l IMMAs
        uint4 bl0 = *(const uint4*)(base + 6144 + boff0);
        uint4 bl1 = *(const uint4*)(base + 6144 + boff1);
        imma(cx[0][0], ah0, bl0.x, bl0.y); imma(cx[0][1], ah0, bl0.z, bl0.w);
        imma(cx[0][2], ah0, bl1.x, bl1.y); imma(cx[0][3], ah0, bl1.z, bl1.w);
        imma(cx[1][0], ah1, bl0.x, bl0.y); imma(cx[1][1], ah1, bl0.z, bl0.w);
        imma(cx[1][2], ah1, bl1.x, bl1.y); imma(cx[1][3], ah1, bl1.z, bl1.w);
        // phase 3: al + l*h IMMAs
        uint4 al0 = *(const uint4*)(base + 2048 + aoff0);
        uint4 al1 = *(const uint4*)(base + 2048 + aoff1);
        imma(cx[0][0], al0, bh0.x, bh0.y); imma(cx[0][1], al0, bh0.z, bh0.w);
        imma(cx[0][2], al0, bh1.x, bh1.y); imma(cx[0][3], al0, bh1.z, bh1.w);
        imma(cx[1][0], al1, bh0.x, bh0.y); imma(cx[1][1], al1, bh0.z, bh0.w);
        imma(cx[1][2], al1, bh1.x, bh1.y); imma(cx[1][3], al1, bh1.z, bh1.w);
    }

    // ---- epilogue: scale, shuffle-pack to float4, 30 replicas of STG.128 ----
    const int bm0 = cm * 64;
    const int bn0 = cn * 64;
    const float kq = 1.0f / 16129.0f;       // 1/(127*127)
    const float kl = 1.0f / 128.0f;
    const int odd = lane & 1;
    #pragma unroll
    for (int mt = 0; mt < 2; mt++) {
        const int rown = bm0 + wm * 32 + mt * 16 + (lane >> 2);
        const float sa0 = __int_as_float(g_sa[rown]) * kq;
        const float sa1 = __int_as_float(g_sa[rown + 8]) * kq;
        const int row_st = rown + (odd << 3);
        #pragma unroll
        for (int nt = 0; nt < 4; nt++) {
            const int colq = bn0 + wn * 32 + nt * 8 + (lane & 3) * 2;
            const float sb0 = __int_as_float(g_sb[colq]);
            const float sb1 = __int_as_float(g_sb[colq + 1]);
            const float v0 = ((float)chh[mt][nt][0] + (float)cx[mt][nt][0] * kl) * sa0 * sb0;
            const float v1 = ((float)chh[mt][nt][1] + (float)cx[mt][nt][1] * kl) * sa0 * sb1;
            const float v2 = ((float)chh[mt][nt][2] + (float)cx[mt][nt][2] * kl) * sa1 * sb0;
            const float v3 = ((float)chh[mt][nt][3] + (float)cx[mt][nt][3] * kl) * sa1 * sb1;
            const float rx = __shfl_xor_sync(0xffffffffu, v0, 1);
            const float ry = __shfl_xor_sync(0xffffffffu, v1, 1);
            const float rz = __shfl_xor_sync(0xffffffffu, v2, 1);
            const float rw = __shfl_xor_sync(0xffffffffu, v3, 1);
            float4 v;
            v.x = odd ? rz : v0;
            v.y = odd ? rw : v1;
            v.z = odd ? v2 : rx;
            v.w = odd ? v3 : ry;
            const int col_st = bn0 + wn * 32 + nt * 8 + (lane & 2) * 2;
            float* p = out + (size_t)row_st * OUTN + col_st;
            #pragma unroll
            for (int rep = 0; rep < NREP; rep++) {
                __stcs((float4*)(p + (size_t)rep * NDIM), v);
            }
        }
    }
}

extern "C" void kernel_launch(void* const* d_in, const int* in_sizes, int n_in,
                              void* d_out, int out_size) {
    const float* x1 = (const float*)d_in[0];
    const float* x2 = (const float*)d_in[1];
    float* out = (float*)d_out;

    scales_kernel<<<1024, 256>>>(x1, x2);
    prep_kernel<<<3072, 256>>>(x1, x2);
    Model_82454782148931_gemm<<<2048, 128>>>(out);   // 32 m x 64 n tiles, m fastest
}

// round 17
// speedup vs baseline: 1.2152x; 1.2152x over previous
#include <cuda_runtime.h>
#include <cstdint>

// out[2048,122880] = tile(x1[2048,4096] @ x2[4096,4096], 30x), fp32.
// R17 = R15 gemm+prep (best: 469us, rel_err 1.2e-4) with ONLY R16's faster
// fully-parallel scales kernel. Single-variable change from the 469 baseline.
#define MDIM 2048
#define NDIM 4096
#define KDIM 4096
#define NREP 30
#define OUTN (NDIM * NREP)
#define NKG (KDIM / 32)          // 128 k32 groups

// fragment-ordered int8 operands
__device__ uint4 g_Ah[(size_t)128 * 128 * 32];   // [m16][k32][lane]
__device__ uint4 g_Al[(size_t)128 * 128 * 32];
__device__ uint4 g_Bh[(size_t)256 * 128 * 32];   // [n16pair][k32][lane]
__device__ uint4 g_Bl[(size_t)256 * 128 * 32];
__device__ int   g_sa[MDIM];                     // row maxabs of A (float-as-int, >=0)
__device__ int   g_sb[NDIM];                     // col maxabs of B (float-as-int, >=0)

__device__ __forceinline__ uint32_t smem_u32(const void* p) {
    uint32_t a;
    asm("{ .reg .u64 t; cvta.to.shared.u64 t, %1; cvt.u32.u64 %0, t; }" : "=r"(a) : "l"(p));
    return a;
}
__device__ __forceinline__ void cp_async16(uint32_t dst, const void* src) {
    asm volatile("cp.async.cg.shared.global [%0], [%1], 16;" :: "r"(dst), "l"(src) : "memory");
}
#define CP_COMMIT() asm volatile("cp.async.commit_group;" ::: "memory")
#define CP_WAIT2()  asm volatile("cp.async.wait_group 2;" ::: "memory")

__device__ __forceinline__ void imma(int c[4], uint4 a, uint32_t b0, uint32_t b1) {
    asm volatile(
        "mma.sync.aligned.m16n8k32.row.col.s32.s8.s8.s32 "
        "{%0,%1,%2,%3},{%4,%5,%6,%7},{%8,%9},{%0,%1,%2,%3};"
        : "+r"(c[0]), "+r"(c[1]), "+r"(c[2]), "+r"(c[3])
        : "r"(a.x), "r"(a.y), "r"(a.z), "r"(a.w), "r"(b0), "r"(b1));
}

// ---------------- kernel 1: scales, fully parallel (R16 version, 22us) ----------------
__global__ __launch_bounds__(256)
void scales_kernel(const float* __restrict__ A, const float* __restrict__ B) {
    const int tid = threadIdx.x, lane = tid & 31, warp = tid >> 5;
    if (blockIdx.x < 512) {
        const int m    = blockIdx.x * 4 + (warp >> 1);
        const int half = warp & 1;
        const float4* a4 = (const float4*)(A + (size_t)m * KDIM + half * 2048);
        float mx = 0.0f;
        #pragma unroll 4
        for (int i = 0; i < 16; i++) {
            float4 v = a4[lane + i * 32];
            mx = fmaxf(mx, fmaxf(fmaxf(fabsf(v.x), fabsf(v.y)),
                                 fmaxf(fabsf(v.z), fabsf(v.w))));
        }
        #pragma unroll
        for (int o = 16; o; o >>= 1) mx = fmaxf(mx, __shfl_xor_sync(0xffffffffu, mx, o));
        if (lane == 0) atomicMax(&g_sa[m], __float_as_int(mx));
    } else {
        const int id = blockIdx.x - 512;
        const int kc = id >> 4;           // 0..31, 128 rows each
        const int nc = id & 15;           // 0..15, 256 cols each
        const int n  = nc * 256 + tid;
        const float* __restrict__ bp = B + (size_t)(kc * 128) * NDIM + n;
        float mx = 0.0f;
        #pragma unroll 8
        for (int k = 0; k < 128; k++)
            mx = fmaxf(mx, fabsf(bp[(size_t)k * NDIM]));
        atomicMax(&g_sb[n], __float_as_int(mx));
    }
}

__device__ __forceinline__ uint32_t pack4(const int h[4]) {
    return (uint32_t)(h[0] & 0xff) | ((uint32_t)(h[1] & 0xff) << 8) |
           ((uint32_t)(h[2] & 0xff) << 16) | ((uint32_t)(h[3] & 0xff) << 24);
}

// ---------------- kernel 2: quantize + fragment-pack (R15 version) ----------------
__global__ __launch_bounds__(256)
void prep_kernel(const float* __restrict__ A, const float* __restrict__ B) {
    __shared__ float sbuf[128 * 68];     // A view 16x516, B view 128x68
    __shared__ float inv_s[64];
    const int tid = threadIdx.x, lane = tid & 31, warp = tid >> 5;
    const int g = lane >> 2, t = lane & 3;

    if (blockIdx.x < 1024) {
        const int bx = blockIdx.x & 7;    // K/512
        const int m16 = blockIdx.x >> 3;  // M/16
        #pragma unroll
        for (int i = 0; i < 8; i++) {
            const int idx = i * 256 + tid;
            const int rr = idx >> 7, c4 = idx & 127;
            *(float4*)&sbuf[rr * 516 + c4 * 4] =
                *(const float4*)&A[(size_t)(m16 * 16 + rr) * KDIM + bx * 512 + c4 * 4];
        }
        if (tid < 16) {
            float mx = __int_as_float(g_sa[m16 * 16 + tid]);
            inv_s[tid] = mx > 0.0f ? 127.0f / mx : 0.0f;
        }
        __syncthreads();
        const float ia0 = inv_s[g], ia1 = inv_s[g + 8];
        auto pk = [&](int row, int c0, float ia, uint32_t& h4, uint32_t& l4) {
            int hh[4], ll[4];
            #pragma unroll
            for (int j = 0; j < 4; j++) {
                float q = sbuf[row * 516 + c0 + j] * ia;
                float hf = rintf(q);
                hh[j] = (int)hf;
                ll[j] = (int)rintf((q - hf) * 128.0f);
            }
            h4 = pack4(hh); l4 = pack4(ll);
        };
        #pragma unroll
        for (int i = 0; i < 2; i++) {
            const int kgl = warp * 2 + i;        // 0..15
            const int kb = kgl * 32;
            uint4 H, L;
            pk(g,     kb + 4 * t,      ia0, H.x, L.x);
            pk(g + 8, kb + 4 * t,      ia1, H.y, L.y);
            pk(g,     kb + 16 + 4 * t, ia0, H.z, L.z);
            pk(g + 8, kb + 16 + 4 * t, ia1, H.w, L.w);
            const size_t o = ((size_t)m16 * 128 + bx * 16 + kgl) * 32 + lane;
            g_Ah[o] = H; g_Al[o] = L;
        }
    } else {
        const int id = blockIdx.x - 1024;
        const int bx = id & 31;           // K/128
        const int by = id >> 5;           // N/64
        #pragma unroll
        for (int i = 0; i < 8; i++) {
            const int idx = i * 256 + tid;
            const int kr = idx >> 4, c4 = idx & 15;
            *(float4*)&sbuf[kr * 68 + c4 * 4] =
                *(const float4*)&B[(size_t)(bx * 128 + kr) * NDIM + by * 64 + c4 * 4];
        }
        if (tid < 64) {
            float mx = __int_as_float(g_sb[by * 64 + tid]);
            inv_s[tid] = mx > 0.0f ? 127.0f / mx : 0.0f;
        }
        __syncthreads();
        auto pk = [&](int col, int k0, float ib, uint32_t& h4, uint32_t& l4) {
            int hh[4], ll[4];
            #pragma unroll
            for (int j = 0; j < 4; j++) {
                float q = sbuf[(k0 + j) * 68 + col] * ib;
                float hf = rintf(q);
                hh[j] = (int)hf;
                ll[j] = (int)rintf((q - hf) * 128.0f);
            }
            h4 = pack4(hh); l4 = pack4(ll);
        };
        #pragma unroll
        for (int i = 0; i < 2; i++) {
            const int id2 = warp * 2 + i;        // 16 items: 4 n16p x 4 kgl
            const int n16l = id2 >> 2, kgl = id2 & 3;
            const int c0 = n16l * 16 + g, c1 = c0 + 8;
            const float ib0 = inv_s[c0], ib1 = inv_s[c1];
            const int kb = kgl * 32;
            uint4 H, L;
            pk(c0, kb + 4 * t,      ib0, H.x, L.x);
            pk(c0, kb + 16 + 4 * t, ib0, H.y, L.y);
            pk(c1, kb + 4 * t,      ib1, H.z, L.z);
            pk(c1, kb + 16 + 4 * t, ib1, H.w, L.w);
            const size_t o = (((size_t)by * 4 + n16l) * 128 + bx * 4 + kgl) * 32 + lane;
            g_Bh[o] = H; g_Bl[o] = L;
        }
    }
}

// ---------------- GEMM (R15 version): 64x64 CTA, 4 warps, int8 split, 4-stage ----------
// stage (8KB): Ah@0 Al@2048 Bh@4096 Bl@6144, each 128 uint4
__global__ __launch_bounds__(128, 4)
void Model_82454782148931_gemm(float* __restrict__ out) {
    __shared__ char smem[4 * 8192];
    const uint32_t sbase = smem_u32(smem);
    const int tid  = threadIdx.x;
    const int lane = tid & 31;
    const int warp = tid >> 5;
    const int wm   = warp & 1;              // 0..1 -> 32-row slab
    const int wn   = warp >> 1;             // 0..1 -> 32-col slab
    const int cm   = blockIdx.x & 31;       // m fastest: wave shares A in L2
    const int cn   = blockIdx.x >> 5;       // 0..63
    const int bm16c  = cm * 4;              // 4 m16 tiles per CTA
    const int bn16pc = cn * 4;              // 4 n16-pair tiles per CTA

    int chh[2][4][4], cx[2][4][4];
    #pragma unroll
    for (int mt = 0; mt < 2; mt++)
        #pragma unroll
        for (int nt = 0; nt < 4; nt++)
            #pragma unroll
            for (int i = 0; i < 4; i++) { chh[mt][nt][i] = 0; cx[mt][nt][i] = 0; }

    const int m16l = tid >> 5;              // thread's load row-tile (=warp)
    const int ln   = tid & 31;
    auto load_stage = [&](int s, int kt) {
        const uint32_t ab = sbase + s * 8192;
        cp_async16(ab + tid * 16,        &g_Ah[((size_t)(bm16c + m16l) * 128 + kt) * 32 + ln]);
        cp_async16(ab + 2048 + tid * 16, &g_Al[((size_t)(bm16c + m16l) * 128 + kt) * 32 + ln]);
        cp_async16(ab + 4096 + tid * 16, &g_Bh[((size_t)(bn16pc + m16l) * 128 + kt) * 32 + ln]);
        cp_async16(ab + 6144 + tid * 16, &g_Bl[((size_t)(bn16pc + m16l) * 128 + kt) * 32 + ln]);
    };

    load_stage(0, 0); CP_COMMIT();
    load_stage(1, 1); CP_COMMIT();
    load_stage(2, 2); CP_COMMIT();

    #pragma unroll 1
    for (int kt = 0; kt < NKG; kt++) {
        const int s = kt & 3;
        CP_WAIT2();
        __syncthreads();
        if (kt + 3 < NKG) load_stage((kt + 3) & 3, kt + 3);
        CP_COMMIT();

        const char* base = smem + s * 8192;
        uint4 ah[2], al[2], bh[2], bl[2];
        #pragma unroll
        for (int mt = 0; mt < 2; mt++) {
            const int off = ((wm * 2 + mt) * 32 + lane) * 16;
            ah[mt] = *(const uint4*)(base + off);
            al[mt] = *(const uint4*)(base + 2048 + off);
        }
        #pragma unroll
        for (int p = 0; p < 2; p++) {
            const int off = ((wn * 2 + p) * 32 + lane) * 16;
            bh[p] = *(const uint4*)(base + 4096 + off);
            bl[p] = *(const uint4*)(base + 6144 + off);
        }
        #pragma unroll
        for (int mt = 0; mt < 2; mt++)
            #pragma unroll
            for (int p = 0; p < 2; p++) {
                const int nt = p * 2;
                imma(chh[mt][nt],     ah[mt], bh[p].x, bh[p].y);   // hh
                imma(chh[mt][nt + 1], ah[mt], bh[p].z, bh[p].w);
                imma(cx[mt][nt],      ah[mt], bl[p].x, bl[p].y);   // h*l
                imma(cx[mt][nt + 1],  ah[mt], bl[p].z, bl[p].w);
                imma(cx[mt][nt],      al[mt], bh[p].x, bh[p].y);   // l*h
                imma(cx[mt][nt + 1],  al[mt], bh[p].z, bh[p].w);
            }
    }

    // ---- epilogue: scale, then 30 replicas of full-sector float2 __stcs ----
    const int bm0 = cm * 64;
    const int bn0 = cn * 64;
    const float kq = 1.0f / 16129.0f;       // 1/(127*127)
    const float kl = 1.0f / 128.0f;
    #pragma unroll
    for (int mt = 0; mt < 2; mt++) {
        const int row0 = bm0 + wm * 32 + mt * 16 + (lane >> 2);
        const float sa0 = __int_as_float(g_sa[row0]) * kq;
        const float sa1 = __int_as_float(g_sa[row0 + 8]) * kq;
        #pragma unroll
        for (int nt = 0; nt < 4; nt++) {
            const int col = bn0 + wn * 32 + nt * 8 + (lane & 3) * 2;
            const float sb0 = __int_as_float(g_sb[col]);
            const float sb1 = __int_as_float(g_sb[col + 1]);
            const float v0 = ((float)chh[mt][nt][0] + (float)cx[mt][nt][0] * kl) * sa0 * sb0;
            const float v1 = ((float)chh[mt][nt][1] + (float)cx[mt][nt][1] * kl) * sa0 * sb1;
            const float v2 = ((float)chh[mt][nt][2] + (float)cx[mt][nt][2] * kl) * sa1 * sb0;
            const float v3 = ((float)chh[mt][nt][3] + (float)cx[mt][nt][3] * kl) * sa1 * sb1;
            const float2 v01 = make_float2(v0, v1);
            const float2 v23 = make_float2(v2, v3);
            float* p0 = out + (size_t)row0 * OUTN + col;
            float* p1 = p0 + (size_t)8 * OUTN;
            #pragma unroll
            for (int rep = 0; rep < NREP; rep++) {
                __stcs((float2*)(p0 + (size_t)rep * NDIM), v01);
                __stcs((float2*)(p1 + (size_t)rep * NDIM), v23);
            }
        }
    }
}

extern "C" void kernel_launch(void* const* d_in, const int* in_sizes, int n_in,
                              void* d_out, int out_size) {
    const float* x1 = (const float*)d_in[0];
    const float* x2 = (const float*)d_in[1];
    float* out = (float*)d_out;

    scales_kernel<<<1024, 256>>>(x1, x2);
    prep_kernel<<<3072, 256>>>(x1, x2);
    Model_82454782148931_gemm<<<2048, 128>>>(out);   // 32 m x 64 n tiles, m fastest
}